// round 1
// baseline (speedup 1.0000x reference)
#include <cuda_runtime.h>
#include <math.h>

#define IMG_W 128
#define IMG_H 128
#define MAX_N 4096

// Scratch: 16 floats per gaussian (4 x float4):
//  [0] minu, maxu, minv, maxv   (bounding box, trunc'd, clamped at 0 for mins)
//  [1] u, v, ia, ibc            (center + inverse-cov terms; ibc = ib+ic)
//  [2] idd, op, z, (pad)
//  [3] col0, col1, col2, (pad)
__device__ float4 g_prm[MAX_N * 4];

__global__ void gs_precompute(const float* __restrict__ means,
                              const float* __restrict__ scales,
                              const float* __restrict__ rots,
                              const float* __restrict__ opac,
                              const float* __restrict__ feats,
                              const float* __restrict__ cam,
                              const float* __restrict__ focal_p,
                              const float* __restrict__ cx_p,
                              const float* __restrict__ cy_p,
                              int N)
{
    int g = blockIdx.x * blockDim.x + threadIdx.x;
    if (g >= N) return;

    const float f  = focal_p[0];
    const float cx = cx_p[0];
    const float cy = cy_p[0];

    // camera
    float R[3][3], t[3];
    #pragma unroll
    for (int i = 0; i < 3; i++) {
        #pragma unroll
        for (int k = 0; k < 3; k++) R[i][k] = cam[i * 4 + k];
        t[i] = cam[i * 4 + 3];
    }

    float mean[3], sc[3];
    #pragma unroll
    for (int k = 0; k < 3; k++) {
        mean[k] = means[g * 3 + k];
        sc[k]   = expf(scales[g * 3 + k]);
    }

    // quaternion -> rotation (reference's non-normalized two_s form)
    float qw = rots[g * 4 + 0], qx = rots[g * 4 + 1];
    float qy = rots[g * 4 + 2], qz = rots[g * 4 + 3];
    float two_s = 2.0f / (qw * qw + qx * qx + qy * qy + qz * qz);
    float xx = qx * qx * two_s, xy = qx * qy * two_s, xz = qx * qz * two_s;
    float yw = qy * qw * two_s, yy = qy * qy * two_s, yz = qy * qz * two_s;
    float zw = qz * qw * two_s, zz = qz * qz * two_s, xw = qx * qw * two_s;
    float M[3][3];
    M[0][0] = 1.0f - (yy + zz); M[0][1] = xy - zw;          M[0][2] = xz + yw;
    M[1][0] = xy + zw;          M[1][1] = 1.0f - (xx + zz); M[1][2] = yz - xw;
    M[2][0] = xz - yw;          M[2][1] = yz + xw;          M[2][2] = 1.0f - (xx + yy);

    // camera-space mean: means @ R.T + t
    float mc[3];
    #pragma unroll
    for (int i = 0; i < 3; i++)
        mc[i] = R[i][0] * mean[0] + R[i][1] * mean[1] + R[i][2] * mean[2] + t[i];
    float z = mc[2];
    float u = mc[0] / z * f + cx;
    float v = mc[1] / z * f + cy;

    // J = [[f,0,-cx],[0,f,-cy],[0,0,1]] @ R   (rows 0,1 only)
    float J0[3], J1[3];
    #pragma unroll
    for (int k = 0; k < 3; k++) {
        J0[k] = f * R[0][k] - cx * R[2][k];
        J1[k] = f * R[1][k] - cy * R[2][k];
    }

    // V[i][k] = (sum_j J_i[j] * M[j][k]) * sc[k]
    float V0[3], V1[3];
    #pragma unroll
    for (int k = 0; k < 3; k++) {
        V0[k] = (J0[0] * M[0][k] + J0[1] * M[1][k] + J0[2] * M[2][k]) * sc[k];
        V1[k] = (J1[0] * M[0][k] + J1[1] * M[1][k] + J1[2] * M[2][k]) * sc[k];
    }

    float inv_z2 = 1.0f / (z * z);
    float a = (V0[0] * V0[0] + V0[1] * V0[1] + V0[2] * V0[2]) * inv_z2;
    float b = (V0[0] * V1[0] + V0[1] * V1[1] + V0[2] * V1[2]) * inv_z2;
    float d = (V1[0] * V1[0] + V1[1] * V1[1] + V1[2] * V1[2]) * inv_z2;
    float det = a * d - b * b;
    float ia  = d / det;
    float ibc = -(b + b) / det;   // (ib + ic) = -(b + c)/det with b == c
    float idd = a / det;

    float op = 1.0f / (1.0f + expf(-opac[g]));
    float c0 = 1.0f / (1.0f + expf(-feats[g * 3 + 0]));
    float c1 = 1.0f / (1.0f + expf(-feats[g * 3 + 1]));
    float c2 = 1.0f / (1.0f + expf(-feats[g * 3 + 2]));

    float smax = fmaxf(sc[0], fmaxf(sc[1], sc[2]));
    float radius = smax * f / z * 3.0f;

    float minu = fmaxf(0.0f, truncf(u - radius));
    float maxu = truncf(u + radius);
    float minv = fmaxf(0.0f, truncf(v - radius));
    float maxv = truncf(v + radius);

    g_prm[g * 4 + 0] = make_float4(minu, maxu, minv, maxv);
    g_prm[g * 4 + 1] = make_float4(u, v, ia, ibc);
    g_prm[g * 4 + 2] = make_float4(idd, op, z, 0.0f);
    g_prm[g * 4 + 3] = make_float4(c0, c1, c2, 0.0f);
}

// 16x8 pixel tile per 128-thread block; all gaussian params staged in smem.
__global__ void gs_render(float* __restrict__ out, int N)
{
    extern __shared__ float4 sg[];
    const int tid  = threadIdx.y * blockDim.x + threadIdx.x;
    const int nthr = blockDim.x * blockDim.y;

    for (int i = tid; i < N * 4; i += nthr) sg[i] = g_prm[i];
    __syncthreads();

    const int px_i = blockIdx.x * 16 + threadIdx.x;
    const int py_i = blockIdx.y * 8  + threadIdx.y;
    const float px = (float)px_i;
    const float py = (float)py_i;

    float img0 = 0.0f, img1 = 0.0f, img2 = 0.0f;
    float alpha_buf = 0.0f;
    float depth_buf = __int_as_float(0x7f800000);  // +inf

    for (int g = 0; g < N; g++) {
        float4 box = sg[g * 4 + 0];
        if (px < box.x || px > box.y || py < box.z || py > box.w) continue;

        float4 B = sg[g * 4 + 1];   // u, v, ia, ibc
        float4 C = sg[g * 4 + 2];   // idd, op, z
        float dx = px - B.x;
        float dy = py - B.y;
        float d2 = B.z * dx * dx + B.w * dx * dy + C.x * dy * dy;
        if (d2 < 9.0f && C.z < depth_buf) {
            float a  = C.y * expf(-0.5f * d2);
            float na = a * (1.0f - alpha_buf);
            float4 D = sg[g * 4 + 3];  // colors
            float om = 1.0f - na;
            img0 = img0 * om + D.x * na;
            img1 = img1 * om + D.y * na;
            img2 = img2 * om + D.z * na;
            alpha_buf += na;
            depth_buf = C.z;
        }
    }

    int base = (py_i * IMG_W + px_i) * 3;
    out[base + 0] = img0;
    out[base + 1] = img1;
    out[base + 2] = img2;
}

extern "C" void kernel_launch(void* const* d_in, const int* in_sizes, int n_in,
                              void* d_out, int out_size)
{
    const float* means  = (const float*)d_in[0];
    const float* scales = (const float*)d_in[1];
    const float* rots   = (const float*)d_in[2];
    const float* opac   = (const float*)d_in[3];
    const float* feats  = (const float*)d_in[4];
    const float* cam    = (const float*)d_in[5];
    const float* focal  = (const float*)d_in[6];
    const float* cx     = (const float*)d_in[7];
    const float* cy     = (const float*)d_in[8];
    float* out = (float*)d_out;

    int N = in_sizes[0] / 3;
    if (N > MAX_N) N = MAX_N;

    gs_precompute<<<(N + 255) / 256, 256>>>(means, scales, rots, opac, feats,
                                            cam, focal, cx, cy, N);

    size_t smem = (size_t)N * 4 * sizeof(float4);  // 64 KB for N=1024
    static bool attr_set = false;
    cudaFuncSetAttribute(gs_render, cudaFuncAttributeMaxDynamicSharedMemorySize,
                         (int)(MAX_N * 4 * sizeof(float4) < 65536 ? 65536
                               : 65536));
    // (attribute call is idempotent and not a stream op; safe under capture)
    (void)attr_set;

    dim3 block(16, 8);
    dim3 grid(IMG_W / 16, IMG_H / 8);
    gs_render<<<grid, block, smem>>>(out, N);
}

// round 2
// speedup vs baseline: 1.8293x; 1.8293x over previous
#include <cuda_runtime.h>
#include <math.h>

#define IMG_W 128
#define IMG_H 128
#define MAX_N 4096
#define CH    256          // cull chunk size (gaussians per staging pass)
#define TILE_W 8
#define TILE_H 4

// Per-gaussian params, 4 x float4:
//  [0] minu, maxu, minv, maxv   (bbox, trunc'd; mins clamped at 0)
//  [1] u, v, ia, ibc            (center + inverse-cov; ibc = ib+ic)
//  [2] idd, op, z, pad
//  [3] col0, col1, col2, pad
__device__ float4 g_prm[MAX_N * 4];

__global__ void gs_precompute(const float* __restrict__ means,
                              const float* __restrict__ scales,
                              const float* __restrict__ rots,
                              const float* __restrict__ opac,
                              const float* __restrict__ feats,
                              const float* __restrict__ cam,
                              const float* __restrict__ focal_p,
                              const float* __restrict__ cx_p,
                              const float* __restrict__ cy_p,
                              int N)
{
    int g = blockIdx.x * blockDim.x + threadIdx.x;
    if (g >= N) return;

    const float f  = focal_p[0];
    const float cx = cx_p[0];
    const float cy = cy_p[0];

    float R[3][3], t[3];
    #pragma unroll
    for (int i = 0; i < 3; i++) {
        #pragma unroll
        for (int k = 0; k < 3; k++) R[i][k] = cam[i * 4 + k];
        t[i] = cam[i * 4 + 3];
    }

    float mean[3], sc[3];
    #pragma unroll
    for (int k = 0; k < 3; k++) {
        mean[k] = means[g * 3 + k];
        sc[k]   = expf(scales[g * 3 + k]);
    }

    float qw = rots[g * 4 + 0], qx = rots[g * 4 + 1];
    float qy = rots[g * 4 + 2], qz = rots[g * 4 + 3];
    float two_s = 2.0f / (qw * qw + qx * qx + qy * qy + qz * qz);
    float xx = qx * qx * two_s, xy = qx * qy * two_s, xz = qx * qz * two_s;
    float yw = qy * qw * two_s, yy = qy * qy * two_s, yz = qy * qz * two_s;
    float zw = qz * qw * two_s, zz = qz * qz * two_s, xw = qx * qw * two_s;
    float M[3][3];
    M[0][0] = 1.0f - (yy + zz); M[0][1] = xy - zw;          M[0][2] = xz + yw;
    M[1][0] = xy + zw;          M[1][1] = 1.0f - (xx + zz); M[1][2] = yz - xw;
    M[2][0] = xz - yw;          M[2][1] = yz + xw;          M[2][2] = 1.0f - (xx + yy);

    float mc[3];
    #pragma unroll
    for (int i = 0; i < 3; i++)
        mc[i] = R[i][0] * mean[0] + R[i][1] * mean[1] + R[i][2] * mean[2] + t[i];
    float z = mc[2];
    float u = mc[0] / z * f + cx;
    float v = mc[1] / z * f + cy;

    float J0[3], J1[3];
    #pragma unroll
    for (int k = 0; k < 3; k++) {
        J0[k] = f * R[0][k] - cx * R[2][k];
        J1[k] = f * R[1][k] - cy * R[2][k];
    }

    float V0[3], V1[3];
    #pragma unroll
    for (int k = 0; k < 3; k++) {
        V0[k] = (J0[0] * M[0][k] + J0[1] * M[1][k] + J0[2] * M[2][k]) * sc[k];
        V1[k] = (J1[0] * M[0][k] + J1[1] * M[1][k] + J1[2] * M[2][k]) * sc[k];
    }

    float inv_z2 = 1.0f / (z * z);
    float a = (V0[0] * V0[0] + V0[1] * V0[1] + V0[2] * V0[2]) * inv_z2;
    float b = (V0[0] * V1[0] + V0[1] * V1[1] + V0[2] * V1[2]) * inv_z2;
    float d = (V1[0] * V1[0] + V1[1] * V1[1] + V1[2] * V1[2]) * inv_z2;
    float det = a * d - b * b;
    float ia  = d / det;
    float ibc = -(b + b) / det;
    float idd = a / det;

    float op = 1.0f / (1.0f + expf(-opac[g]));
    float c0 = 1.0f / (1.0f + expf(-feats[g * 3 + 0]));
    float c1 = 1.0f / (1.0f + expf(-feats[g * 3 + 1]));
    float c2 = 1.0f / (1.0f + expf(-feats[g * 3 + 2]));

    float smax = fmaxf(sc[0], fmaxf(sc[1], sc[2]));
    float radius = smax * f / z * 3.0f;

    float minu = fmaxf(0.0f, truncf(u - radius));
    float maxu = truncf(u + radius);
    float minv = fmaxf(0.0f, truncf(v - radius));
    float maxv = truncf(v + radius);

    g_prm[g * 4 + 0] = make_float4(minu, maxu, minv, maxv);
    g_prm[g * 4 + 1] = make_float4(u, v, ia, ibc);
    g_prm[g * 4 + 2] = make_float4(idd, op, z, 0.0f);
    g_prm[g * 4 + 3] = make_float4(c0, c1, c2, 0.0f);
}

// One warp per 8x4 pixel tile. Chunked order-preserving cull into smem,
// then per-pixel loop over the compacted list.
__global__ __launch_bounds__(32, 14)
void gs_render(float* __restrict__ out, int N)
{
    __shared__ float4 sl[CH * 4];

    const int lane = threadIdx.x;              // 0..31
    const int tx0  = blockIdx.x * TILE_W;
    const int ty0  = blockIdx.y * TILE_H;
    const int px_i = tx0 + (lane & (TILE_W - 1));
    const int py_i = ty0 + (lane >> 3);
    const float px = (float)px_i;
    const float py = (float)py_i;

    // tile bounds as floats for overlap test against bbox
    const float ftx0 = (float)tx0, ftx1 = (float)(tx0 + TILE_W - 1);
    const float fty0 = (float)ty0, fty1 = (float)(ty0 + TILE_H - 1);

    float img0 = 0.0f, img1 = 0.0f, img2 = 0.0f;
    float alpha_buf = 0.0f;
    float depth_buf = __int_as_float(0x7f800000);  // +inf

    for (int base = 0; base < N; base += CH) {
        // ---- cull: compact overlapping gaussians of this chunk, order kept ----
        int cnt = 0;
        #pragma unroll 2
        for (int j0 = 0; j0 < CH; j0 += 32) {
            int g = base + j0 + lane;
            bool ok = false;
            float4 box;
            if (g < N) {
                box = g_prm[g * 4 + 0];
                ok = (box.x <= ftx1) & (box.y >= ftx0) &
                     (box.z <= fty1) & (box.w >= fty0);
            }
            unsigned m = __ballot_sync(0xffffffffu, ok);
            if (ok) {
                int p = cnt + __popc(m & ((1u << lane) - 1u));
                sl[p * 4 + 0] = box;
                sl[p * 4 + 1] = g_prm[g * 4 + 1];
                sl[p * 4 + 2] = g_prm[g * 4 + 2];
                sl[p * 4 + 3] = g_prm[g * 4 + 3];
            }
            cnt += __popc(m);
        }
        __syncwarp();

        // ---- composite over compacted list (cnt is warp-uniform) ----
        for (int i = 0; i < cnt; i++) {
            float4 box = sl[i * 4 + 0];
            float4 B   = sl[i * 4 + 1];   // u, v, ia, ibc
            float4 C   = sl[i * 4 + 2];   // idd, op, z
            float dx = px - B.x;
            float dy = py - B.y;
            float d2 = B.z * dx * dx + B.w * dx * dy + C.x * dy * dy;
            bool inb = (px >= box.x) & (px <= box.y) &
                       (py >= box.z) & (py <= box.w);
            if (inb & (d2 < 9.0f) & (C.z < depth_buf)) {
                float a  = C.y * __expf(-0.5f * d2);
                float na = a * (1.0f - alpha_buf);
                float4 D = sl[i * 4 + 3];
                float om = 1.0f - na;
                img0 = img0 * om + D.x * na;
                img1 = img1 * om + D.y * na;
                img2 = img2 * om + D.z * na;
                alpha_buf += na;
                depth_buf = C.z;
            }
        }
        __syncwarp();
    }

    int idx = (py_i * IMG_W + px_i) * 3;
    out[idx + 0] = img0;
    out[idx + 1] = img1;
    out[idx + 2] = img2;
}

extern "C" void kernel_launch(void* const* d_in, const int* in_sizes, int n_in,
                              void* d_out, int out_size)
{
    const float* means  = (const float*)d_in[0];
    const float* scales = (const float*)d_in[1];
    const float* rots   = (const float*)d_in[2];
    const float* opac   = (const float*)d_in[3];
    const float* feats  = (const float*)d_in[4];
    const float* cam    = (const float*)d_in[5];
    const float* focal  = (const float*)d_in[6];
    const float* cx     = (const float*)d_in[7];
    const float* cy     = (const float*)d_in[8];
    float* out = (float*)d_out;

    int N = in_sizes[0] / 3;
    if (N > MAX_N) N = MAX_N;

    gs_precompute<<<(N + 255) / 256, 256>>>(means, scales, rots, opac, feats,
                                            cam, focal, cx, cy, N);

    dim3 block(32, 1);
    dim3 grid(IMG_W / TILE_W, IMG_H / TILE_H);  // 16 x 32 = 512 blocks
    gs_render<<<grid, block>>>(out, N);
}

// round 3
// speedup vs baseline: 2.2891x; 1.2513x over previous
#include <cuda_runtime.h>
#include <math.h>

#define IMG_W 128
#define IMG_H 128
#define MAX_N 4096
#define TILE_W 8
#define TILE_H 4
#define SEGS   8
#define SLOTS  16

// Per-gaussian params, 4 x float4:
//  [0] minu, maxu, minv, maxv   (bbox, trunc'd; mins clamped at 0)
//  [1] u, v, ia, ibc            (center + inverse-cov; ibc = ib+ic)
//  [2] idd, op, z, pad
//  [3] col0, col1, col2, pad
__device__ float4 g_prm[MAX_N * 4];

__global__ void gs_precompute(const float* __restrict__ means,
                              const float* __restrict__ scales,
                              const float* __restrict__ rots,
                              const float* __restrict__ opac,
                              const float* __restrict__ feats,
                              const float* __restrict__ cam,
                              const float* __restrict__ focal_p,
                              const float* __restrict__ cx_p,
                              const float* __restrict__ cy_p,
                              int N)
{
    int g = blockIdx.x * blockDim.x + threadIdx.x;
    if (g >= N) return;

    const float f  = focal_p[0];
    const float cx = cx_p[0];
    const float cy = cy_p[0];

    float R[3][3], t[3];
    #pragma unroll
    for (int i = 0; i < 3; i++) {
        #pragma unroll
        for (int k = 0; k < 3; k++) R[i][k] = cam[i * 4 + k];
        t[i] = cam[i * 4 + 3];
    }

    float mean[3], sc[3];
    #pragma unroll
    for (int k = 0; k < 3; k++) {
        mean[k] = means[g * 3 + k];
        sc[k]   = expf(scales[g * 3 + k]);
    }

    float qw = rots[g * 4 + 0], qx = rots[g * 4 + 1];
    float qy = rots[g * 4 + 2], qz = rots[g * 4 + 3];
    float two_s = 2.0f / (qw * qw + qx * qx + qy * qy + qz * qz);
    float xx = qx * qx * two_s, xy = qx * qy * two_s, xz = qx * qz * two_s;
    float yw = qy * qw * two_s, yy = qy * qy * two_s, yz = qy * qz * two_s;
    float zw = qz * qw * two_s, zz = qz * qz * two_s, xw = qx * qw * two_s;
    float M[3][3];
    M[0][0] = 1.0f - (yy + zz); M[0][1] = xy - zw;          M[0][2] = xz + yw;
    M[1][0] = xy + zw;          M[1][1] = 1.0f - (xx + zz); M[1][2] = yz - xw;
    M[2][0] = xz - yw;          M[2][1] = yz + xw;          M[2][2] = 1.0f - (xx + yy);

    float mc[3];
    #pragma unroll
    for (int i = 0; i < 3; i++)
        mc[i] = R[i][0] * mean[0] + R[i][1] * mean[1] + R[i][2] * mean[2] + t[i];
    float z = mc[2];
    float u = mc[0] / z * f + cx;
    float v = mc[1] / z * f + cy;

    float J0[3], J1[3];
    #pragma unroll
    for (int k = 0; k < 3; k++) {
        J0[k] = f * R[0][k] - cx * R[2][k];
        J1[k] = f * R[1][k] - cy * R[2][k];
    }

    float V0[3], V1[3];
    #pragma unroll
    for (int k = 0; k < 3; k++) {
        V0[k] = (J0[0] * M[0][k] + J0[1] * M[1][k] + J0[2] * M[2][k]) * sc[k];
        V1[k] = (J1[0] * M[0][k] + J1[1] * M[1][k] + J1[2] * M[2][k]) * sc[k];
    }

    float inv_z2 = 1.0f / (z * z);
    float a = (V0[0] * V0[0] + V0[1] * V0[1] + V0[2] * V0[2]) * inv_z2;
    float b = (V0[0] * V1[0] + V0[1] * V1[1] + V0[2] * V1[2]) * inv_z2;
    float d = (V1[0] * V1[0] + V1[1] * V1[1] + V1[2] * V1[2]) * inv_z2;
    float det = a * d - b * b;
    float ia  = d / det;
    float ibc = -(b + b) / det;
    float idd = a / det;

    float op = 1.0f / (1.0f + expf(-opac[g]));
    float c0 = 1.0f / (1.0f + expf(-feats[g * 3 + 0]));
    float c1 = 1.0f / (1.0f + expf(-feats[g * 3 + 1]));
    float c2 = 1.0f / (1.0f + expf(-feats[g * 3 + 2]));

    float smax = fmaxf(sc[0], fmaxf(sc[1], sc[2]));
    float radius = smax * f / z * 3.0f;

    float minu = fmaxf(0.0f, truncf(u - radius));
    float maxu = truncf(u + radius);
    float minv = fmaxf(0.0f, truncf(v - radius));
    float maxv = truncf(v + radius);

    g_prm[g * 4 + 0] = make_float4(minu, maxu, minv, maxv);
    g_prm[g * 4 + 1] = make_float4(u, v, ia, ibc);
    g_prm[g * 4 + 2] = make_float4(idd, op, z, 0.0f);
    g_prm[g * 4 + 3] = make_float4(c0, c1, c2, 0.0f);
}

// 8 warps per 8x4 tile. Each warp owns a contiguous gaussian segment:
// culls it, then (lane = pixel) records local strict-running-min candidates
// (z, a, idx) into smem. Warp 0 then merges segments in order with the
// global running-min (== reference depth_buf) and composites.
__global__ __launch_bounds__(SEGS * 32, 4)
void gs_render(float* __restrict__ out, int N)
{
    extern __shared__ char smem_raw[];
    float* s_ent = (float*)smem_raw;                         // [SEGS][SLOTS][32][3]
    int*   s_cnt = (int*)(s_ent + SEGS * SLOTS * 32 * 3);    // [SEGS][32]
    unsigned short* s_idx = (unsigned short*)(s_cnt + SEGS * 32);

    const int warp = threadIdx.x >> 5;
    const int lane = threadIdx.x & 31;

    const int segLen = (N + SEGS - 1) / SEGS;
    const int segBeg = warp * segLen;
    const int segEnd = min(segBeg + segLen, N);

    const int tx0 = blockIdx.x * TILE_W;
    const int ty0 = blockIdx.y * TILE_H;
    const int px_i = tx0 + (lane & (TILE_W - 1));
    const int py_i = ty0 + (lane >> 3);
    const float px = (float)px_i;
    const float py = (float)py_i;
    const float ftx0 = (float)tx0, ftx1 = (float)(tx0 + TILE_W - 1);
    const float fty0 = (float)ty0, fty1 = (float)(ty0 + TILE_H - 1);

    // ---- cull this warp's segment (order-preserving compaction) ----
    unsigned short* myidx = s_idx + warp * segLen;
    int cnt = 0;
    for (int j = segBeg; j < segEnd; j += 32) {
        int g = j + lane;
        bool ok = false;
        if (g < segEnd) {
            float4 box = g_prm[g * 4 + 0];
            ok = (box.x <= ftx1) & (box.y >= ftx0) &
                 (box.z <= fty1) & (box.w >= fty0);
        }
        unsigned m = __ballot_sync(0xffffffffu, ok);
        if (ok) myidx[cnt + __popc(m & ((1u << lane) - 1u))] = (unsigned short)g;
        cnt += __popc(m);
    }

    // ---- phase A: record local strict running minima per pixel ----
    float runmin = __int_as_float(0x7f800000);  // +inf
    int mycnt = 0;
    for (int i = 0; i < cnt; i++) {
        int g = myidx[i];
        float4 box = __ldg(&g_prm[g * 4 + 0]);
        float4 B   = __ldg(&g_prm[g * 4 + 1]);   // u, v, ia, ibc
        float4 C   = __ldg(&g_prm[g * 4 + 2]);   // idd, op, z
        float dx = px - B.x;
        float dy = py - B.y;
        float d2 = B.z * dx * dx + B.w * dx * dy + C.x * dy * dy;
        bool inb = (px >= box.x) & (px <= box.y) &
                   (py >= box.z) & (py <= box.w);
        if (inb & (d2 < 9.0f)) {
            if (C.z < runmin) {
                runmin = C.z;
                if (mycnt < SLOTS) {
                    float a = C.y * __expf(-0.5f * d2);
                    int b = ((warp * SLOTS + mycnt) * 32 + lane) * 3;
                    s_ent[b + 0] = C.z;
                    s_ent[b + 1] = a;
                    s_ent[b + 2] = __int_as_float(g);
                    mycnt++;
                }
            }
        }
    }
    s_cnt[warp * 32 + lane] = mycnt;
    __syncthreads();

    // ---- phase B: ordered merge + composite (warp 0, lane = pixel) ----
    if (warp == 0) {
        float i0 = 0.0f, i1 = 0.0f, i2 = 0.0f;
        float ab = 0.0f;
        float d  = __int_as_float(0x7f800000);  // +inf
        for (int s = 0; s < SEGS; s++) {
            int c = s_cnt[s * 32 + lane];
            for (int j = 0; j < c; j++) {
                int b = ((s * SLOTS + j) * 32 + lane) * 3;
                float z = s_ent[b + 0];
                float a = s_ent[b + 1];
                int   g = __float_as_int(s_ent[b + 2]);
                if (z < d) {
                    float4 D = __ldg(&g_prm[g * 4 + 3]);
                    float na = a * (1.0f - ab);
                    float om = 1.0f - na;
                    i0 = i0 * om + D.x * na;
                    i1 = i1 * om + D.y * na;
                    i2 = i2 * om + D.z * na;
                    ab += na;
                    d = z;
                }
            }
        }
        int o = (py_i * IMG_W + px_i) * 3;
        out[o + 0] = i0;
        out[o + 1] = i1;
        out[o + 2] = i2;
    }
}

extern "C" void kernel_launch(void* const* d_in, const int* in_sizes, int n_in,
                              void* d_out, int out_size)
{
    const float* means  = (const float*)d_in[0];
    const float* scales = (const float*)d_in[1];
    const float* rots   = (const float*)d_in[2];
    const float* opac   = (const float*)d_in[3];
    const float* feats  = (const float*)d_in[4];
    const float* cam    = (const float*)d_in[5];
    const float* focal  = (const float*)d_in[6];
    const float* cx     = (const float*)d_in[7];
    const float* cy     = (const float*)d_in[8];
    float* out = (float*)d_out;

    int N = in_sizes[0] / 3;
    if (N > MAX_N) N = MAX_N;

    gs_precompute<<<(N + 255) / 256, 256>>>(means, scales, rots, opac, feats,
                                            cam, focal, cx, cy, N);

    int segLen = (N + SEGS - 1) / SEGS;
    size_t smem = (size_t)SEGS * SLOTS * 32 * 3 * sizeof(float)   // entries
                + (size_t)SEGS * 32 * sizeof(int)                 // counts
                + (size_t)SEGS * segLen * sizeof(unsigned short); // index lists
    cudaFuncSetAttribute(gs_render, cudaFuncAttributeMaxDynamicSharedMemorySize,
                         100 * 1024);

    dim3 block(SEGS * 32, 1);
    dim3 grid(IMG_W / TILE_W, IMG_H / TILE_H);  // 16 x 32 = 512 blocks
    gs_render<<<grid, block, smem>>>(out, N);
}

// round 4
// speedup vs baseline: 2.9203x; 1.2757x over previous
#include <cuda_runtime.h>
#include <math.h>

#define IMG_W 128
#define IMG_H 128
#define MAX_N 4096
#define TILE_W 8
#define TILE_H 4
#define SEGS   8
#define SLOTS  16
#define NBLK   ((IMG_W / TILE_W) * (IMG_H / TILE_H))   // 512

// Per-gaussian params, 4 x float4:
//  [0] minu, maxu, minv, maxv
//  [1] u, v, ia, ibc
//  [2] idd, op, z, pad
//  [3] col0, col1, col2, pad
__device__ float4 g_prm[MAX_N * 4];

// Global record scratch (L2-resident for the live part):
//  entA[bid][seg][slot][lane] = (z, a, c0, c1) ; entB = c2
__device__ float4 g_entA[NBLK * SEGS * SLOTS * 32];
__device__ float  g_entB[NBLK * SEGS * SLOTS * 32];

__global__ void gs_precompute(const float* __restrict__ means,
                              const float* __restrict__ scales,
                              const float* __restrict__ rots,
                              const float* __restrict__ opac,
                              const float* __restrict__ feats,
                              const float* __restrict__ cam,
                              const float* __restrict__ focal_p,
                              const float* __restrict__ cx_p,
                              const float* __restrict__ cy_p,
                              int N)
{
    int g = blockIdx.x * blockDim.x + threadIdx.x;
    if (g >= N) return;

    const float f  = focal_p[0];
    const float cx = cx_p[0];
    const float cy = cy_p[0];

    float R[3][3], t[3];
    #pragma unroll
    for (int i = 0; i < 3; i++) {
        #pragma unroll
        for (int k = 0; k < 3; k++) R[i][k] = cam[i * 4 + k];
        t[i] = cam[i * 4 + 3];
    }

    float mean[3], sc[3];
    #pragma unroll
    for (int k = 0; k < 3; k++) {
        mean[k] = means[g * 3 + k];
        sc[k]   = expf(scales[g * 3 + k]);
    }

    float qw = rots[g * 4 + 0], qx = rots[g * 4 + 1];
    float qy = rots[g * 4 + 2], qz = rots[g * 4 + 3];
    float two_s = 2.0f / (qw * qw + qx * qx + qy * qy + qz * qz);
    float xx = qx * qx * two_s, xy = qx * qy * two_s, xz = qx * qz * two_s;
    float yw = qy * qw * two_s, yy = qy * qy * two_s, yz = qy * qz * two_s;
    float zw = qz * qw * two_s, zz = qz * qz * two_s, xw = qx * qw * two_s;
    float M[3][3];
    M[0][0] = 1.0f - (yy + zz); M[0][1] = xy - zw;          M[0][2] = xz + yw;
    M[1][0] = xy + zw;          M[1][1] = 1.0f - (xx + zz); M[1][2] = yz - xw;
    M[2][0] = xz - yw;          M[2][1] = yz + xw;          M[2][2] = 1.0f - (xx + yy);

    float mc[3];
    #pragma unroll
    for (int i = 0; i < 3; i++)
        mc[i] = R[i][0] * mean[0] + R[i][1] * mean[1] + R[i][2] * mean[2] + t[i];
    float z = mc[2];
    float u = mc[0] / z * f + cx;
    float v = mc[1] / z * f + cy;

    float J0[3], J1[3];
    #pragma unroll
    for (int k = 0; k < 3; k++) {
        J0[k] = f * R[0][k] - cx * R[2][k];
        J1[k] = f * R[1][k] - cy * R[2][k];
    }

    float V0[3], V1[3];
    #pragma unroll
    for (int k = 0; k < 3; k++) {
        V0[k] = (J0[0] * M[0][k] + J0[1] * M[1][k] + J0[2] * M[2][k]) * sc[k];
        V1[k] = (J1[0] * M[0][k] + J1[1] * M[1][k] + J1[2] * M[2][k]) * sc[k];
    }

    float inv_z2 = 1.0f / (z * z);
    float a = (V0[0] * V0[0] + V0[1] * V0[1] + V0[2] * V0[2]) * inv_z2;
    float b = (V0[0] * V1[0] + V0[1] * V1[1] + V0[2] * V1[2]) * inv_z2;
    float d = (V1[0] * V1[0] + V1[1] * V1[1] + V1[2] * V1[2]) * inv_z2;
    float det = a * d - b * b;
    float ia  = d / det;
    float ibc = -(b + b) / det;
    float idd = a / det;

    float op = 1.0f / (1.0f + expf(-opac[g]));
    float c0 = 1.0f / (1.0f + expf(-feats[g * 3 + 0]));
    float c1 = 1.0f / (1.0f + expf(-feats[g * 3 + 1]));
    float c2 = 1.0f / (1.0f + expf(-feats[g * 3 + 2]));

    float smax = fmaxf(sc[0], fmaxf(sc[1], sc[2]));
    float radius = smax * f / z * 3.0f;

    float minu = fmaxf(0.0f, truncf(u - radius));
    float maxu = truncf(u + radius);
    float minv = fmaxf(0.0f, truncf(v - radius));
    float maxv = truncf(v + radius);

    g_prm[g * 4 + 0] = make_float4(minu, maxu, minv, maxv);
    g_prm[g * 4 + 1] = make_float4(u, v, ia, ibc);
    g_prm[g * 4 + 2] = make_float4(idd, op, z, 0.0f);
    g_prm[g * 4 + 3] = make_float4(c0, c1, c2, 0.0f);
}

// 8 warps / 8x4 tile. Phase A: each warp culls+scans its gaussian segment,
// records local strict-running-min candidates (z, a, rgb) to global scratch.
// Phase B: warp 0 (lane = pixel) merges segments in order with the global
// running-min (== reference depth_buf) and composites from the records.
__global__ __launch_bounds__(SEGS * 32)
void gs_render(float* __restrict__ out, int N)
{
    extern __shared__ char smem_raw[];
    int* s_cnt = (int*)smem_raw;                        // [SEGS][32]
    unsigned short* s_idx = (unsigned short*)(s_cnt + SEGS * 32);

    const int warp = threadIdx.x >> 5;
    const int lane = threadIdx.x & 31;
    const int bid  = blockIdx.y * gridDim.x + blockIdx.x;

    const int segLen = (N + SEGS - 1) / SEGS;
    const int segBeg = warp * segLen;
    const int segEnd = min(segBeg + segLen, N);

    const int tx0 = blockIdx.x * TILE_W;
    const int ty0 = blockIdx.y * TILE_H;
    const int px_i = tx0 + (lane & (TILE_W - 1));
    const int py_i = ty0 + (lane >> 3);
    const float px = (float)px_i;
    const float py = (float)py_i;
    const float ftx0 = (float)tx0, ftx1 = (float)(tx0 + TILE_W - 1);
    const float fty0 = (float)ty0, fty1 = (float)(ty0 + TILE_H - 1);

    // ---- cull segment (order-preserving compaction of indices) ----
    unsigned short* myidx = s_idx + warp * segLen;
    int cnt = 0;
    for (int j = segBeg; j < segEnd; j += 32) {
        int g = j + lane;
        bool ok = false;
        if (g < segEnd) {
            float4 box = __ldg(&g_prm[g * 4 + 0]);
            ok = (box.x <= ftx1) & (box.y >= ftx0) &
                 (box.z <= fty1) & (box.w >= fty0);
        }
        unsigned m = __ballot_sync(0xffffffffu, ok);
        if (ok) myidx[cnt + __popc(m & ((1u << lane) - 1u))] = (unsigned short)g;
        cnt += __popc(m);
    }

    // ---- phase A: local strict running minima, records -> global scratch ----
    const int entBase = ((bid * SEGS + warp) * SLOTS) * 32 + lane;
    float runmin = __int_as_float(0x7f800000);  // +inf
    int mycnt = 0;
    for (int i = 0; i < cnt; i++) {
        int g = myidx[i];
        float4 box = __ldg(&g_prm[g * 4 + 0]);
        float4 B   = __ldg(&g_prm[g * 4 + 1]);   // u, v, ia, ibc
        float4 C   = __ldg(&g_prm[g * 4 + 2]);   // idd, op, z
        float dx = px - B.x;
        float dy = py - B.y;
        float d2 = B.z * dx * dx + B.w * dx * dy + C.x * dy * dy;
        bool inb = (px >= box.x) & (px <= box.y) &
                   (py >= box.z) & (py <= box.w);
        if (inb & (d2 < 9.0f) & (C.z < runmin)) {
            runmin = C.z;
            if (mycnt < SLOTS) {
                float4 D = __ldg(&g_prm[g * 4 + 3]);
                float a = C.y * __expf(-0.5f * d2);
                int e = entBase + mycnt * 32;
                g_entA[e] = make_float4(C.z, a, D.x, D.y);
                g_entB[e] = D.z;
                mycnt++;
            }
        }
    }
    s_cnt[warp * 32 + lane] = mycnt;
    __syncthreads();

    // ---- phase B: ordered merge + composite (warp 0, lane = pixel) ----
    if (warp == 0) {
        float i0 = 0.0f, i1 = 0.0f, i2 = 0.0f;
        float ab = 0.0f;
        float d  = __int_as_float(0x7f800000);  // +inf
        const int pbase = (bid * SEGS * SLOTS) * 32 + lane;
        for (int s = 0; s < SEGS; s++) {
            int c = s_cnt[s * 32 + lane];
            int sb = pbase + s * SLOTS * 32;
            for (int j0 = 0; j0 < c; j0 += 4) {
                // batch-load up to 4 records (independent LDGs, MLP)
                float4 e0, e1, e2, e3;
                float  b0 = 0.f, b1 = 0.f, b2 = 0.f, b3 = 0.f;
                int r = c - j0;
                e0 = g_entA[sb + (j0 + 0) * 32]; b0 = g_entB[sb + (j0 + 0) * 32];
                if (r > 1) { e1 = g_entA[sb + (j0 + 1) * 32]; b1 = g_entB[sb + (j0 + 1) * 32]; }
                if (r > 2) { e2 = g_entA[sb + (j0 + 2) * 32]; b2 = g_entB[sb + (j0 + 2) * 32]; }
                if (r > 3) { e3 = g_entA[sb + (j0 + 3) * 32]; b3 = g_entB[sb + (j0 + 3) * 32]; }

                #pragma unroll
                for (int k = 0; k < 4; k++) {
                    float4 e = (k == 0) ? e0 : (k == 1) ? e1 : (k == 2) ? e2 : e3;
                    float  bc = (k == 0) ? b0 : (k == 1) ? b1 : (k == 2) ? b2 : b3;
                    if (k < r && e.x < d) {
                        float na = e.y * (1.0f - ab);
                        float om = 1.0f - na;
                        i0 = i0 * om + e.z * na;
                        i1 = i1 * om + e.w * na;
                        i2 = i2 * om + bc  * na;
                        ab += na;
                        d = e.x;
                    }
                }
            }
        }
        int o = (py_i * IMG_W + px_i) * 3;
        out[o + 0] = i0;
        out[o + 1] = i1;
        out[o + 2] = i2;
    }
}

extern "C" void kernel_launch(void* const* d_in, const int* in_sizes, int n_in,
                              void* d_out, int out_size)
{
    const float* means  = (const float*)d_in[0];
    const float* scales = (const float*)d_in[1];
    const float* rots   = (const float*)d_in[2];
    const float* opac   = (const float*)d_in[3];
    const float* feats  = (const float*)d_in[4];
    const float* cam    = (const float*)d_in[5];
    const float* focal  = (const float*)d_in[6];
    const float* cx     = (const float*)d_in[7];
    const float* cy     = (const float*)d_in[8];
    float* out = (float*)d_out;

    int N = in_sizes[0] / 3;
    if (N > MAX_N) N = MAX_N;

    gs_precompute<<<(N + 255) / 256, 256>>>(means, scales, rots, opac, feats,
                                            cam, focal, cx, cy, N);

    int segLen = (N + SEGS - 1) / SEGS;
    size_t smem = (size_t)SEGS * 32 * sizeof(int)                 // counts
                + (size_t)SEGS * segLen * sizeof(unsigned short); // index lists
    cudaFuncSetAttribute(gs_render, cudaFuncAttributeMaxDynamicSharedMemorySize,
                         64 * 1024);

    dim3 block(SEGS * 32, 1);
    dim3 grid(IMG_W / TILE_W, IMG_H / TILE_H);  // 16 x 32 = 512 blocks
    gs_render<<<grid, block, smem>>>(out, N);
}

// round 5
// speedup vs baseline: 2.9898x; 1.0238x over previous
#include <cuda_runtime.h>
#include <math.h>

#define IMG_W 128
#define IMG_H 128
#define MAX_N 4096
#define TILE_W 8
#define TILE_H 4
#define SEGS   8
#define SLOTS  16

// Per-gaussian params, 4 x float4:
//  [0] minu, maxu, minv, maxv
//  [1] u, v, ia, ibc
//  [2] idd, op, z, pad
//  [3] col0, col1, col2, pad
__device__ float4 g_prm[MAX_N * 4];

__global__ void gs_precompute(const float* __restrict__ means,
                              const float* __restrict__ scales,
                              const float* __restrict__ rots,
                              const float* __restrict__ opac,
                              const float* __restrict__ feats,
                              const float* __restrict__ cam,
                              const float* __restrict__ focal_p,
                              const float* __restrict__ cx_p,
                              const float* __restrict__ cy_p,
                              int N)
{
    int g = blockIdx.x * blockDim.x + threadIdx.x;
    if (g >= N) return;

    const float f  = focal_p[0];
    const float cx = cx_p[0];
    const float cy = cy_p[0];

    float R[3][3], t[3];
    #pragma unroll
    for (int i = 0; i < 3; i++) {
        #pragma unroll
        for (int k = 0; k < 3; k++) R[i][k] = cam[i * 4 + k];
        t[i] = cam[i * 4 + 3];
    }

    float mean[3], sc[3];
    #pragma unroll
    for (int k = 0; k < 3; k++) {
        mean[k] = means[g * 3 + k];
        sc[k]   = expf(scales[g * 3 + k]);
    }

    float qw = rots[g * 4 + 0], qx = rots[g * 4 + 1];
    float qy = rots[g * 4 + 2], qz = rots[g * 4 + 3];
    float two_s = 2.0f / (qw * qw + qx * qx + qy * qy + qz * qz);
    float xx = qx * qx * two_s, xy = qx * qy * two_s, xz = qx * qz * two_s;
    float yw = qy * qw * two_s, yy = qy * qy * two_s, yz = qy * qz * two_s;
    float zw = qz * qw * two_s, zz = qz * qz * two_s, xw = qx * qw * two_s;
    float M[3][3];
    M[0][0] = 1.0f - (yy + zz); M[0][1] = xy - zw;          M[0][2] = xz + yw;
    M[1][0] = xy + zw;          M[1][1] = 1.0f - (xx + zz); M[1][2] = yz - xw;
    M[2][0] = xz - yw;          M[2][1] = yz + xw;          M[2][2] = 1.0f - (xx + yy);

    float mc[3];
    #pragma unroll
    for (int i = 0; i < 3; i++)
        mc[i] = R[i][0] * mean[0] + R[i][1] * mean[1] + R[i][2] * mean[2] + t[i];
    float z = mc[2];
    float u = mc[0] / z * f + cx;
    float v = mc[1] / z * f + cy;

    float J0[3], J1[3];
    #pragma unroll
    for (int k = 0; k < 3; k++) {
        J0[k] = f * R[0][k] - cx * R[2][k];
        J1[k] = f * R[1][k] - cy * R[2][k];
    }

    float V0[3], V1[3];
    #pragma unroll
    for (int k = 0; k < 3; k++) {
        V0[k] = (J0[0] * M[0][k] + J0[1] * M[1][k] + J0[2] * M[2][k]) * sc[k];
        V1[k] = (J1[0] * M[0][k] + J1[1] * M[1][k] + J1[2] * M[2][k]) * sc[k];
    }

    float inv_z2 = 1.0f / (z * z);
    float a = (V0[0] * V0[0] + V0[1] * V0[1] + V0[2] * V0[2]) * inv_z2;
    float b = (V0[0] * V1[0] + V0[1] * V1[1] + V0[2] * V1[2]) * inv_z2;
    float d = (V1[0] * V1[0] + V1[1] * V1[1] + V1[2] * V1[2]) * inv_z2;
    float det = a * d - b * b;
    float ia  = d / det;
    float ibc = -(b + b) / det;
    float idd = a / det;

    float op = 1.0f / (1.0f + expf(-opac[g]));
    float c0 = 1.0f / (1.0f + expf(-feats[g * 3 + 0]));
    float c1 = 1.0f / (1.0f + expf(-feats[g * 3 + 1]));
    float c2 = 1.0f / (1.0f + expf(-feats[g * 3 + 2]));

    float smax = fmaxf(sc[0], fmaxf(sc[1], sc[2]));
    float radius = smax * f / z * 3.0f;

    float minu = fmaxf(0.0f, truncf(u - radius));
    float maxu = truncf(u + radius);
    float minv = fmaxf(0.0f, truncf(v - radius));
    float maxv = truncf(v + radius);

    g_prm[g * 4 + 0] = make_float4(minu, maxu, minv, maxv);
    g_prm[g * 4 + 1] = make_float4(u, v, ia, ibc);
    g_prm[g * 4 + 2] = make_float4(idd, op, z, 0.0f);
    g_prm[g * 4 + 3] = make_float4(c0, c1, c2, 0.0f);
}

// 8 warps / 8x4 tile. Phase A: each warp culls its gaussian segment, then
// (lane = pixel) records local strict-running-min candidates (z, a, gid)
// into smem, 4-wide batched + predicated. Phase B: warp 0 merges segments
// in order with the global running-min, fully branchless composite.
__global__ __launch_bounds__(SEGS * 32, 4)
void gs_render(float* __restrict__ out, int N)
{
    __shared__ float2         s_rec[SEGS * SLOTS * 32];  // (z, a)   32 KB
    __shared__ unsigned short s_gid[SEGS * SLOTS * 32];  // gaussian  8 KB
    __shared__ int            s_cnt[SEGS * 32];          //           1 KB
    extern __shared__ unsigned short s_idx[];            // per-seg index lists

    const int warp = threadIdx.x >> 5;
    const int lane = threadIdx.x & 31;

    const int segLen = (N + SEGS - 1) / SEGS;
    const int segBeg = warp * segLen;
    const int segEnd = min(segBeg + segLen, N);

    const int tx0 = blockIdx.x * TILE_W;
    const int ty0 = blockIdx.y * TILE_H;
    const int px_i = tx0 + (lane & (TILE_W - 1));
    const int py_i = ty0 + (lane >> 3);
    const float px = (float)px_i;
    const float py = (float)py_i;
    const float ftx0 = (float)tx0, ftx1 = (float)(tx0 + TILE_W - 1);
    const float fty0 = (float)ty0, fty1 = (float)(ty0 + TILE_H - 1);
    const float INF = __int_as_float(0x7f800000);

    // ---- cull segment (order-preserving index compaction) ----
    unsigned short* myidx = s_idx + warp * segLen;
    int cnt = 0;
    for (int j = segBeg; j < segEnd; j += 32) {
        int g = j + lane;
        bool ok = false;
        if (g < segEnd) {
            float4 box = __ldg(&g_prm[g * 4 + 0]);
            ok = (box.x <= ftx1) & (box.y >= ftx0) &
                 (box.z <= fty1) & (box.w >= fty0);
        }
        unsigned m = __ballot_sync(0xffffffffu, ok);
        if (ok) myidx[cnt + __popc(m & ((1u << lane) - 1u))] = (unsigned short)g;
        cnt += __popc(m);
    }

    // ---- phase A: local strict running minima -> smem records ----
    const int entBase = warp * SLOTS * 32 + lane;
    float runmin = INF;
    int mycnt = 0;
    for (int i0 = 0; i0 < cnt; i0 += 4) {
        int r = cnt - i0;
        int gg[4]; float4 bx[4], B[4], C[4];
        #pragma unroll
        for (int k = 0; k < 4; k++) {
            int idx = (k < r) ? (int)myidx[i0 + k] : 0;
            gg[k] = idx & (MAX_N - 1);
            bx[k] = __ldg(&g_prm[gg[k] * 4 + 0]);
            B[k]  = __ldg(&g_prm[gg[k] * 4 + 1]);
            C[k]  = __ldg(&g_prm[gg[k] * 4 + 2]);
        }
        #pragma unroll
        for (int k = 0; k < 4; k++) {
            float dx = px - B[k].x;
            float dy = py - B[k].y;
            float d2 = B[k].z * dx * dx + B[k].w * dx * dy + C[k].x * dy * dy;
            bool inb = (px >= bx[k].x) & (px <= bx[k].y) &
                       (py >= bx[k].z) & (py <= bx[k].w);
            bool acc = (k < r) & inb & (d2 < 9.0f) & (C[k].z < runmin);
            float a  = C[k].y * __expf(-0.5f * d2);  // speculative, MUFU
            if (acc) {
                runmin = C[k].z;
                if (mycnt < SLOTS) {
                    s_rec[entBase + mycnt * 32] = make_float2(C[k].z, a);
                    s_gid[entBase + mycnt * 32] = (unsigned short)gg[k];
                }
                mycnt++;
            }
        }
    }
    s_cnt[warp * 32 + lane] = min(mycnt, SLOTS);
    __syncthreads();

    // ---- phase B: ordered merge + branchless composite (warp 0) ----
    if (warp == 0) {
        float i0v = 0.0f, i1v = 0.0f, i2v = 0.0f;
        float ab = 0.0f;
        float d  = INF;
        #pragma unroll 1
        for (int s = 0; s < SEGS; s++) {
            int c = s_cnt[s * 32 + lane];
            int cmax = __reduce_max_sync(0xffffffffu, c);
            int base = s * SLOTS * 32 + lane;
            for (int j0 = 0; j0 < cmax; j0 += 4) {
                float2 rec[4]; float4 col[4]; bool val[4];
                #pragma unroll
                for (int k = 0; k < 4; k++) {
                    int j = j0 + k;
                    int e = base + min(j, SLOTS - 1) * 32;
                    val[k] = (j < c);
                    rec[k] = s_rec[e];
                    int gid = (int)s_gid[e] & (MAX_N - 1);
                    col[k] = __ldg(&g_prm[gid * 4 + 3]);
                }
                #pragma unroll
                for (int k = 0; k < 4; k++) {
                    bool t  = val[k] & (rec[k].x < d);
                    float na = t ? rec[k].y * (1.0f - ab) : 0.0f;
                    float om = 1.0f - na;
                    i0v = i0v * om + col[k].x * na;
                    i1v = i1v * om + col[k].y * na;
                    i2v = i2v * om + col[k].z * na;
                    ab += na;
                    d = t ? rec[k].x : d;
                }
            }
        }
        int o = (py_i * IMG_W + px_i) * 3;
        out[o + 0] = i0v;
        out[o + 1] = i1v;
        out[o + 2] = i2v;
    }
}

extern "C" void kernel_launch(void* const* d_in, const int* in_sizes, int n_in,
                              void* d_out, int out_size)
{
    const float* means  = (const float*)d_in[0];
    const float* scales = (const float*)d_in[1];
    const float* rots   = (const float*)d_in[2];
    const float* opac   = (const float*)d_in[3];
    const float* feats  = (const float*)d_in[4];
    const float* cam    = (const float*)d_in[5];
    const float* focal  = (const float*)d_in[6];
    const float* cx     = (const float*)d_in[7];
    const float* cy     = (const float*)d_in[8];
    float* out = (float*)d_out;

    int N = in_sizes[0] / 3;
    if (N > MAX_N) N = MAX_N;

    gs_precompute<<<(N + 255) / 256, 256>>>(means, scales, rots, opac, feats,
                                            cam, focal, cx, cy, N);

    int segLen = (N + SEGS - 1) / SEGS;
    size_t smem = (size_t)SEGS * segLen * sizeof(unsigned short);
    cudaFuncSetAttribute(gs_render, cudaFuncAttributeMaxDynamicSharedMemorySize,
                         32 * 1024);

    dim3 block(SEGS * 32, 1);
    dim3 grid(IMG_W / TILE_W, IMG_H / TILE_H);  // 16 x 32 = 512 blocks
    gs_render<<<grid, block, smem>>>(out, N);
}

// round 6
// speedup vs baseline: 3.2022x; 1.0710x over previous
#include <cuda_runtime.h>
#include <math.h>

#define IMG_W 128
#define IMG_H 128
#define MAX_N 4096
#define TILE_W 8
#define TILE_H 4
#define SEGS   16
#define SLOTS  16

// Per-gaussian params, 4 x float4:
//  [0] minu, maxu, minv, maxv    (reference box - used in pixel mask)
//  [1] u, v, ia, ibc
//  [2] idd, op, z, pad
//  [3] col0, col1, col2, pad
__device__ float4 g_prm[MAX_N * 4];
// Tightened cull box (refbox ∩ 3-sigma ellipse extents) - cull only.
__device__ float4 g_cbox[MAX_N];

__global__ void gs_precompute(const float* __restrict__ means,
                              const float* __restrict__ scales,
                              const float* __restrict__ rots,
                              const float* __restrict__ opac,
                              const float* __restrict__ feats,
                              const float* __restrict__ cam,
                              const float* __restrict__ focal_p,
                              const float* __restrict__ cx_p,
                              const float* __restrict__ cy_p,
                              int N)
{
    int g = blockIdx.x * blockDim.x + threadIdx.x;
    if (g >= N) return;

    const float f  = focal_p[0];
    const float cx = cx_p[0];
    const float cy = cy_p[0];

    float R[3][3], t[3];
    #pragma unroll
    for (int i = 0; i < 3; i++) {
        #pragma unroll
        for (int k = 0; k < 3; k++) R[i][k] = cam[i * 4 + k];
        t[i] = cam[i * 4 + 3];
    }

    float mean[3], sc[3];
    #pragma unroll
    for (int k = 0; k < 3; k++) {
        mean[k] = means[g * 3 + k];
        sc[k]   = expf(scales[g * 3 + k]);
    }

    float qw = rots[g * 4 + 0], qx = rots[g * 4 + 1];
    float qy = rots[g * 4 + 2], qz = rots[g * 4 + 3];
    float two_s = 2.0f / (qw * qw + qx * qx + qy * qy + qz * qz);
    float xx = qx * qx * two_s, xy = qx * qy * two_s, xz = qx * qz * two_s;
    float yw = qy * qw * two_s, yy = qy * qy * two_s, yz = qy * qz * two_s;
    float zw = qz * qw * two_s, zz = qz * qz * two_s, xw = qx * qw * two_s;
    float M[3][3];
    M[0][0] = 1.0f - (yy + zz); M[0][1] = xy - zw;          M[0][2] = xz + yw;
    M[1][0] = xy + zw;          M[1][1] = 1.0f - (xx + zz); M[1][2] = yz - xw;
    M[2][0] = xz - yw;          M[2][1] = yz + xw;          M[2][2] = 1.0f - (xx + yy);

    float mc[3];
    #pragma unroll
    for (int i = 0; i < 3; i++)
        mc[i] = R[i][0] * mean[0] + R[i][1] * mean[1] + R[i][2] * mean[2] + t[i];
    float z = mc[2];
    float u = mc[0] / z * f + cx;
    float v = mc[1] / z * f + cy;

    float J0[3], J1[3];
    #pragma unroll
    for (int k = 0; k < 3; k++) {
        J0[k] = f * R[0][k] - cx * R[2][k];
        J1[k] = f * R[1][k] - cy * R[2][k];
    }

    float V0[3], V1[3];
    #pragma unroll
    for (int k = 0; k < 3; k++) {
        V0[k] = (J0[0] * M[0][k] + J0[1] * M[1][k] + J0[2] * M[2][k]) * sc[k];
        V1[k] = (J1[0] * M[0][k] + J1[1] * M[1][k] + J1[2] * M[2][k]) * sc[k];
    }

    float inv_z2 = 1.0f / (z * z);
    float a = (V0[0] * V0[0] + V0[1] * V0[1] + V0[2] * V0[2]) * inv_z2;
    float b = (V0[0] * V1[0] + V0[1] * V1[1] + V0[2] * V1[2]) * inv_z2;
    float d = (V1[0] * V1[0] + V1[1] * V1[1] + V1[2] * V1[2]) * inv_z2;
    float det = a * d - b * b;
    float ia  = d / det;
    float ibc = -(b + b) / det;
    float idd = a / det;

    float op = 1.0f / (1.0f + expf(-opac[g]));
    float c0 = 1.0f / (1.0f + expf(-feats[g * 3 + 0]));
    float c1 = 1.0f / (1.0f + expf(-feats[g * 3 + 1]));
    float c2 = 1.0f / (1.0f + expf(-feats[g * 3 + 2]));

    float smax = fmaxf(sc[0], fmaxf(sc[1], sc[2]));
    float radius = smax * f / z * 3.0f;

    float minu = fmaxf(0.0f, truncf(u - radius));
    float maxu = truncf(u + radius);
    float minv = fmaxf(0.0f, truncf(v - radius));
    float maxv = truncf(v + radius);

    g_prm[g * 4 + 0] = make_float4(minu, maxu, minv, maxv);
    g_prm[g * 4 + 1] = make_float4(u, v, ia, ibc);
    g_prm[g * 4 + 2] = make_float4(idd, op, z, 0.0f);
    g_prm[g * 4 + 3] = make_float4(c0, c1, c2, 0.0f);

    // tightened cull box: mask requires in_refbox AND d2<9;
    // d2<9 implies |dx| <= 3*sqrt(cov_xx), |dy| <= 3*sqrt(cov_yy)
    float ru = 3.0f * sqrtf(fmaxf(a, 0.0f));
    float rv = 3.0f * sqrtf(fmaxf(d, 0.0f));
    g_cbox[g] = make_float4(fmaxf(minu, u - ru), fminf(maxu, u + ru),
                            fmaxf(minv, v - rv), fminf(maxv, v + rv));
}

// 16 warps / 8x4 tile. Phase A: each warp culls+scans a 64-gaussian segment,
// (lane = pixel) records local strict-running-min candidates into smem.
// Phase B: warp 0 merges segments in order (global running-min == reference
// depth_buf), branchless composite.
__global__ __launch_bounds__(SEGS * 32, 2)
void gs_render(float* __restrict__ out, int N)
{
    extern __shared__ char smem_raw[];
    float2*         s_rec = (float2*)smem_raw;                  // [SEGS*SLOTS*32]
    int*            s_cnt = (int*)(s_rec + SEGS * SLOTS * 32);  // [SEGS*32]
    unsigned short* s_gid = (unsigned short*)(s_cnt + SEGS * 32);
    unsigned short* s_idx = s_gid + SEGS * SLOTS * 32;          // [SEGS*segLen]

    const int warp = threadIdx.x >> 5;
    const int lane = threadIdx.x & 31;

    const int segLen = (N + SEGS - 1) / SEGS;
    const int segBeg = warp * segLen;
    const int segEnd = min(segBeg + segLen, N);

    const int tx0 = blockIdx.x * TILE_W;
    const int ty0 = blockIdx.y * TILE_H;
    const int px_i = tx0 + (lane & (TILE_W - 1));
    const int py_i = ty0 + (lane >> 3);
    const float px = (float)px_i;
    const float py = (float)py_i;
    const float ftx0 = (float)tx0, ftx1 = (float)(tx0 + TILE_W - 1);
    const float fty0 = (float)ty0, fty1 = (float)(ty0 + TILE_H - 1);
    const float INF = __int_as_float(0x7f800000);

    // ---- cull segment against tightened box (order-preserving) ----
    unsigned short* myidx = s_idx + warp * segLen;
    int cnt = 0;
    for (int j = segBeg; j < segEnd; j += 32) {
        int g = j + lane;
        bool ok = false;
        if (g < segEnd) {
            float4 cb = __ldg(&g_cbox[g]);
            ok = (cb.x <= ftx1) & (cb.y >= ftx0) &
                 (cb.z <= fty1) & (cb.w >= fty0);
        }
        unsigned m = __ballot_sync(0xffffffffu, ok);
        if (ok) myidx[cnt + __popc(m & ((1u << lane) - 1u))] = (unsigned short)g;
        cnt += __popc(m);
    }

    // ---- phase A: local strict running minima -> smem records ----
    const int entBase = warp * SLOTS * 32 + lane;
    float runmin = INF;
    int mycnt = 0;
    for (int i0 = 0; i0 < cnt; i0 += 4) {
        int r = cnt - i0;
        int gg[4]; float4 bx[4], B[4], C[4];
        #pragma unroll
        for (int k = 0; k < 4; k++) {
            int idx = (k < r) ? (int)myidx[i0 + k] : 0;
            gg[k] = idx & (MAX_N - 1);
            bx[k] = __ldg(&g_prm[gg[k] * 4 + 0]);
            B[k]  = __ldg(&g_prm[gg[k] * 4 + 1]);
            C[k]  = __ldg(&g_prm[gg[k] * 4 + 2]);
        }
        #pragma unroll
        for (int k = 0; k < 4; k++) {
            float dx = px - B[k].x;
            float dy = py - B[k].y;
            float d2 = B[k].z * dx * dx + B[k].w * dx * dy + C[k].x * dy * dy;
            bool inb = (px >= bx[k].x) & (px <= bx[k].y) &
                       (py >= bx[k].z) & (py <= bx[k].w);
            bool acc = (k < r) & inb & (d2 < 9.0f) & (C[k].z < runmin);
            float a  = C[k].y * __expf(-0.5f * d2);  // speculative, MUFU
            if (acc) {
                runmin = C[k].z;
                if (mycnt < SLOTS) {
                    s_rec[entBase + mycnt * 32] = make_float2(C[k].z, a);
                    s_gid[entBase + mycnt * 32] = (unsigned short)gg[k];
                }
                mycnt++;
            }
        }
    }
    s_cnt[warp * 32 + lane] = min(mycnt, SLOTS);
    __syncthreads();

    // ---- phase B: ordered merge + branchless composite (warp 0) ----
    if (warp == 0) {
        float i0v = 0.0f, i1v = 0.0f, i2v = 0.0f;
        float ab = 0.0f;
        float d  = INF;
        #pragma unroll 1
        for (int s = 0; s < SEGS; s++) {
            int c = s_cnt[s * 32 + lane];
            int cmax = __reduce_max_sync(0xffffffffu, c);
            int base = s * SLOTS * 32 + lane;
            for (int j0 = 0; j0 < cmax; j0 += 4) {
                float2 rec[4]; float4 col[4]; bool val[4];
                #pragma unroll
                for (int k = 0; k < 4; k++) {
                    int j = j0 + k;
                    int e = base + min(j, SLOTS - 1) * 32;
                    val[k] = (j < c);
                    rec[k] = s_rec[e];
                    int gid = (int)s_gid[e] & (MAX_N - 1);
                    col[k] = __ldg(&g_prm[gid * 4 + 3]);
                }
                #pragma unroll
                for (int k = 0; k < 4; k++) {
                    bool t  = val[k] & (rec[k].x < d);
                    float na = t ? rec[k].y * (1.0f - ab) : 0.0f;
                    float om = 1.0f - na;
                    i0v = i0v * om + col[k].x * na;
                    i1v = i1v * om + col[k].y * na;
                    i2v = i2v * om + col[k].z * na;
                    ab += na;
                    d = t ? rec[k].x : d;
                }
            }
        }
        int o = (py_i * IMG_W + px_i) * 3;
        out[o + 0] = i0v;
        out[o + 1] = i1v;
        out[o + 2] = i2v;
    }
}

extern "C" void kernel_launch(void* const* d_in, const int* in_sizes, int n_in,
                              void* d_out, int out_size)
{
    const float* means  = (const float*)d_in[0];
    const float* scales = (const float*)d_in[1];
    const float* rots   = (const float*)d_in[2];
    const float* opac   = (const float*)d_in[3];
    const float* feats  = (const float*)d_in[4];
    const float* cam    = (const float*)d_in[5];
    const float* focal  = (const float*)d_in[6];
    const float* cx     = (const float*)d_in[7];
    const float* cy     = (const float*)d_in[8];
    float* out = (float*)d_out;

    int N = in_sizes[0] / 3;
    if (N > MAX_N) N = MAX_N;

    gs_precompute<<<(N + 255) / 256, 256>>>(means, scales, rots, opac, feats,
                                            cam, focal, cx, cy, N);

    int segLen = (N + SEGS - 1) / SEGS;
    size_t smem = (size_t)SEGS * SLOTS * 32 * sizeof(float2)          // records
                + (size_t)SEGS * 32 * sizeof(int)                     // counts
                + (size_t)SEGS * SLOTS * 32 * sizeof(unsigned short)  // gids
                + (size_t)SEGS * segLen * sizeof(unsigned short);     // idx lists
    cudaFuncSetAttribute(gs_render, cudaFuncAttributeMaxDynamicSharedMemorySize,
                         110 * 1024);

    dim3 block(SEGS * 32, 1);
    dim3 grid(IMG_W / TILE_W, IMG_H / TILE_H);  // 16 x 32 = 512 blocks
    gs_render<<<grid, block, smem>>>(out, N);
}